// round 5
// baseline (speedup 1.0000x reference)
#include <cuda_runtime.h>
#include <cuda_fp16.h>
#include <cstdint>

#define BMAX 131072

// ---- scratch ----
__device__ float g_qw[(size_t)BMAX * 512];
__device__ uint2 g_b1[5 * 8 * 128 * 8];   // K1 B: [ntile5][kh8][n128][j8], fp16-hi pairs
__device__ uint2 g_b3[16 * 128 * 8];      // K3 B: [kh16][n128][j8]

// ============================================================
// helpers
// ============================================================
__device__ __forceinline__ uint32_t smem_u32(const void* p) {
    uint32_t a;
    asm("{ .reg .u64 t; cvta.to.shared.u64 t, %1; cvt.u32.u64 %0, t; }" : "=r"(a) : "l"(p));
    return a;
}
__device__ __forceinline__ uint32_t hpack(float a, float b) {
    __half2 h = __floats2half2_rn(a, b);
    return *reinterpret_cast<uint32_t*>(&h);
}
// uint4 = { hi(a,b), hi(c,d), lo(a,b), lo(c,d) }  ((a,b)=k0,k1 ; (c,d)=k8,k9)
__device__ __forceinline__ uint4 mk4h(float a, float b, float c, float d) {
    uint4 u;
    u.x = hpack(a, b);
    u.y = hpack(c, d);
    __half2 hx = *reinterpret_cast<__half2*>(&u.x);
    __half2 hy = *reinterpret_cast<__half2*>(&u.y);
    u.z = hpack(a - __half2float(__low2half(hx)), b - __half2float(__high2half(hx)));
    u.w = hpack(c - __half2float(__low2half(hy)), d - __half2float(__high2half(hy)));
    return u;
}
__device__ __forceinline__ void mma_fp16(float* c,
                                         uint32_t a0, uint32_t a1, uint32_t a2, uint32_t a3,
                                         uint32_t b0, uint32_t b1) {
    asm volatile(
        "mma.sync.aligned.m16n8k16.row.col.f32.f16.f16.f32 "
        "{%0,%1,%2,%3},{%4,%5,%6,%7},{%8,%9},{%0,%1,%2,%3};\n"
        : "+f"(c[0]), "+f"(c[1]), "+f"(c[2]), "+f"(c[3])
        : "r"(a0), "r"(a1), "r"(a2), "r"(a3), "r"(b0), "r"(b1));
}
#define CP16(dst, src) \
    asm volatile("cp.async.cg.shared.global [%0], [%1], 16;\n" :: "r"(dst), "l"(src) : "memory")
#define CPCOMMIT() asm volatile("cp.async.commit_group;\n" ::: "memory")
#define CPWAIT0()  asm volatile("cp.async.wait_group 0;\n" ::: "memory")

// ============================================================
// Prep: fold weights -> fp16 (hi plane only), fragment layout.
// j = ks*4+tg -> k-pairs kp=ks*8+tg, kp+4 ; k = kh*32+2*kp (+1)
// ============================================================
__global__ void k_prep_b1(const float* __restrict__ Wc, const float* __restrict__ Wn,
                          const float* __restrict__ Wco) {
    int idx = blockIdx.x * 128 + threadIdx.x;      // 40960
    if (idx >= 5 * 8 * 128 * 8) return;
    int j = idx & 7, n_local = (idx >> 3) & 127, kh = (idx >> 10) & 7, ntile = idx >> 13;
    int n = ntile * 128 + n_local;
    int ks = j >> 2, tg = j & 3, kp = ks * 8 + tg;
    int k0 = kh * 32 + 2 * kp;
    int kk[4] = {k0, k0 + 1, k0 + 8, k0 + 9};
    float v[4];
    if (n < 512) {
        int h = n >> 8, j2 = n & 255;
#pragma unroll
        for (int t = 0; t < 4; t++) {
            float s = 0.f;
#pragma unroll 8
            for (int a = 0; a < 64; a++)
                s = fmaf(Wc[(h * 64 + a) * 256 + kk[t]], Wn[(h * 64 + a) * 256 + j2], s);
            v[t] = s;
        }
    } else {
#pragma unroll
        for (int t = 0; t < 4; t++) v[t] = Wco[(n - 512) * 256 + kk[t]];
    }
    g_b1[idx] = make_uint2(hpack(v[0], v[1]), hpack(v[2], v[3]));
}

__global__ void k_prep_b3(const float* __restrict__ Wo, const float* __restrict__ Wv) {
    int idx = blockIdx.x * 128 + threadIdx.x;      // 16384
    if (idx >= 16 * 128 * 8) return;
    int j = idx & 7, n = (idx >> 3) & 127, kh = idx >> 10;
    int ks = j >> 2, tg = j & 3, kp = ks * 8 + tg;
    int k0 = kh * 32 + 2 * kp;
    int kk[4] = {k0, k0 + 1, k0 + 8, k0 + 9};
    float v[4];
#pragma unroll
    for (int t = 0; t < 4; t++) {
        int k = kk[t];
        int h = k >> 8, ii = k & 255;
        float s = 0.f;
#pragma unroll 8
        for (int d = 0; d < 128; d++)
            s = fmaf(Wo[n * 256 + h * 128 + d], Wv[(h * 128 + d) * 256 + ii], s);
        v[t] = s;
    }
    g_b3[idx] = make_uint2(hpack(v[0], v[1]), hpack(v[2], v[3]));
}

// ============================================================
// K1: 2-pass fp16 GEMM. Tile 128x128, BK=32, 256 thr, 8 warps 64x32.
// A = center fp32 (split hi+lo in-kernel), B = g_b1 (hi only).
// smem/stage: A [128][12] uint4 = 24576 ; B [128][12] uint2 = 12288 -> 36864; x2
// ============================================================
#define K1_STAGE 36864
#define K1_SMEM  (2 * K1_STAGE)

__global__ __launch_bounds__(256) void k_gemm1(const float* __restrict__ Ain,
                                               float* __restrict__ dOut) {
    extern __shared__ __align__(16) char smem[];
    const int tid = threadIdx.x, lid = tid & 31, w = tid >> 5;
    const int g = lid >> 2, tg = lid & 3;
    const int wm = (w & 1) * 64, wnn = (w >> 1) * 32;
    const int bn = blockIdx.x, bm = blockIdx.y;

    const uint2* Bb = g_b1 + (size_t)bn * 8 * 1024;
    const float* Ab = Ain + (size_t)bm * 128 * 256;

    const int arow = tid >> 1, aks = tid & 1;

#define AS_PTR(s, m, j) ((uint4*)(smem + (s) * K1_STAGE + ((m) * 12 + (j)) * 16))
#define BS_PTR(s, n, j) ((uint2*)(smem + (s) * K1_STAGE + 24576 + ((n) * 12 + (j)) * 8))

    float4 Areg[2][4];
    auto loadA = [&](int kh, int slot) {
        const float* base = Ab + (size_t)arow * 256 + kh * 32 + aks * 16;
#pragma unroll
        for (int q = 0; q < 4; q++) Areg[slot][q] = *(const float4*)(base + q * 4);
    };
    auto stsA = [&](int kh, int slot) {
        int st = kh & 1;
        float4 f0 = Areg[slot][0], f1 = Areg[slot][1], f2 = Areg[slot][2], f3 = Areg[slot][3];
        *AS_PTR(st, arow, aks * 4 + 0) = mk4h(f0.x, f0.y, f2.x, f2.y);
        *AS_PTR(st, arow, aks * 4 + 1) = mk4h(f0.z, f0.w, f2.z, f2.w);
        *AS_PTR(st, arow, aks * 4 + 2) = mk4h(f1.x, f1.y, f3.x, f3.y);
        *AS_PTR(st, arow, aks * 4 + 3) = mk4h(f1.z, f1.w, f3.z, f3.w);
    };
    auto cpB = [&](int kh) {
        int st = kh & 1;
        const uint4* src = (const uint4*)(Bb + (size_t)kh * 1024);
#pragma unroll
        for (int i = 0; i < 2; i++) {
            int v = tid + 256 * i;              // 0..511 uint4
            int n = v >> 2, jp = v & 3;
            CP16(smem_u32((char*)BS_PTR(st, n, jp * 2)), src + v);
        }
    };

    cpB(0); CPCOMMIT();
    loadA(0, 0);
    stsA(0, 0);
    loadA(1, 1);
    CPWAIT0();
    __syncthreads();

    float acc[4][4][4];
#pragma unroll
    for (int i = 0; i < 4; i++)
#pragma unroll
        for (int jn = 0; jn < 4; jn++)
#pragma unroll
            for (int r = 0; r < 4; r++) acc[i][jn][r] = 0.f;

    const int NI = 8;
    for (int kh = 0; kh < NI; kh++) {
        const int cur = kh & 1;
        if (kh + 1 < NI) { cpB(kh + 1); CPCOMMIT(); stsA(kh + 1, (kh + 1) & 1); }
        if (kh + 2 < NI) loadA(kh + 2, kh & 1);

#pragma unroll
        for (int ks = 0; ks < 2; ks++) {
            uint2 V[4];
#pragma unroll
            for (int nt = 0; nt < 4; nt++)
                V[nt] = *BS_PTR(cur, wnn + nt * 8 + g, ks * 4 + tg);
#pragma unroll
            for (int mt = 0; mt < 4; mt++) {
                uint4 U0 = *AS_PTR(cur, wm + mt * 16 + g, ks * 4 + tg);
                uint4 U1 = *AS_PTR(cur, wm + mt * 16 + g + 8, ks * 4 + tg);
#pragma unroll
                for (int nt = 0; nt < 4; nt++) {
                    float* c = acc[mt][nt];
                    mma_fp16(c, U0.x, U1.x, U0.y, U1.y, V[nt].x, V[nt].y);  // hi
                    mma_fp16(c, U0.z, U1.z, U0.w, U1.w, V[nt].x, V[nt].y);  // lo
                }
            }
        }
        if (kh + 1 < NI) CPWAIT0();
        __syncthreads();
    }

#pragma unroll
    for (int mt = 0; mt < 4; mt++) {
#pragma unroll
        for (int nt = 0; nt < 4; nt++) {
            const float* c = acc[mt][nt];
            int row = bm * 128 + wm + mt * 16 + g;
            int coll = wnn + nt * 8 + 2 * tg;
            float2 v0 = make_float2(c[0], c[1]);
            float2 v1 = make_float2(c[2], c[3]);
            if (bn < 4) {
                int col = bn * 128 + coll;
                *(float2*)(g_qw + (size_t)row * 512 + col) = v0;
                *(float2*)(g_qw + (size_t)(row + 8) * 512 + col) = v1;
            } else {
                *(float2*)(dOut + (size_t)row * 256 + coll) = v0;
                *(float2*)(dOut + (size_t)(row + 8) * 256 + coll) = v1;
            }
        }
    }
#undef AS_PTR
#undef BS_PTR
}

// ============================================================
// Fused attention + K3. CTA = 64 b-rows, 512 threads.
// Phase 1: attention -> wn in smem (64x520 fp32).
// Phase 2: out[:,128:256] = wn @ McatT (2-pass fp16 mma, B3 streamed).
// ============================================================
#define FS_WN   0
#define FS_NB   133120                   // 4 row slots x 16640 B (reused for B3 dbuf)
#define FS_QW   199680                   // 4 x 2048 B
#define FS_EW   207872                   // 256 B
#define FS_SC   208128                   // 4 x 32 floats
#define FS_AT   208640
#define FS_TOTAL 209152
#define B3_BUF  12288                    // [128][12] uint2

__global__ __launch_bounds__(512) void k_fused(const float* __restrict__ nb_g,
                                               const float* __restrict__ ew_g,
                                               float* __restrict__ dOut) {
    extern __shared__ __align__(16) char smem[];
    const int tid = threadIdx.x;
    float* WN = (float*)(smem + FS_WN);

    // ---------------- Phase 1: attention ----------------
    {
        const int lr = tid >> 7, t = tid & 127;
        const int k = t >> 3, s = t & 7;
        float* nb_s = (float*)(smem + FS_NB + lr * 16640);
        float* qw_s = (float*)(smem + FS_QW + lr * 2048);
        float* ews  = (float*)(smem + FS_EW) + lr * 16;
        float* sc   = (float*)(smem + FS_SC) + lr * 32;
        float* at   = (float*)(smem + FS_AT) + lr * 32;

        for (int it = 0; it < 16; it++) {
            const size_t b = (size_t)blockIdx.x * 64 + it * 4 + lr;
            ((float4*)qw_s)[t] = ((const float4*)(g_qw + b * 512))[t];
            if (t < 16) ews[t] = ew_g[b * 16 + t];
            __syncthreads();

            const float4* nb4 = (const float4*)(nb_g + b * 4096);
            float p0 = 0.f, p1 = 0.f;
#pragma unroll
            for (int j = 0; j < 8; j++) {
                int c4 = s + 8 * j;
                float4 x = nb4[k * 64 + c4];
                *(float4*)&nb_s[k * 260 + c4 * 4] = x;
                float4 q0 = *(const float4*)&qw_s[c4 * 4];
                float4 q1 = *(const float4*)&qw_s[256 + c4 * 4];
                p0 = fmaf(x.x, q0.x, p0); p0 = fmaf(x.y, q0.y, p0);
                p0 = fmaf(x.z, q0.z, p0); p0 = fmaf(x.w, q0.w, p0);
                p1 = fmaf(x.x, q1.x, p1); p1 = fmaf(x.y, q1.y, p1);
                p1 = fmaf(x.z, q1.z, p1); p1 = fmaf(x.w, q1.w, p1);
            }
#pragma unroll
            for (int o = 1; o <= 4; o <<= 1) {
                p0 += __shfl_xor_sync(0xffffffffu, p0, o);
                p1 += __shfl_xor_sync(0xffffffffu, p1, o);
            }
            if (s == 0) {
                sc[k]      = p0 * 0.125f + ews[k];
                sc[16 + k] = p1 * 0.125f + ews[k];
            }
            __syncthreads();

            if (t < 32) {
                int hh = t >> 4, kk = t & 15;
                float v = sc[hh * 16 + kk];
                float m = v;
#pragma unroll
                for (int o = 8; o >= 1; o >>= 1)
                    m = fmaxf(m, __shfl_xor_sync(0xffffffffu, m, o));
                float e = __expf(v - m);
                float sum = e;
#pragma unroll
                for (int o = 8; o >= 1; o >>= 1)
                    sum += __shfl_xor_sync(0xffffffffu, sum, o);
                at[hh * 16 + kk] = e / sum;
            }
            __syncthreads();

            {
                int hh = t >> 6;
                int cc = (t * 4) & 255;
                float4 acc = make_float4(0.f, 0.f, 0.f, 0.f);
#pragma unroll
                for (int kk = 0; kk < 16; kk++) {
                    float wgt = at[hh * 16 + kk];
                    float4 x = *(const float4*)&nb_s[kk * 260 + cc];
                    acc.x = fmaf(wgt, x.x, acc.x);
                    acc.y = fmaf(wgt, x.y, acc.y);
                    acc.z = fmaf(wgt, x.z, acc.z);
                    acc.w = fmaf(wgt, x.w, acc.w);
                }
                *(float4*)&WN[(it * 4 + lr) * 520 + t * 4] = acc;
            }
            __syncthreads();
        }
    }

    // ---------------- Phase 2: K3 GEMM ----------------
    {
        const int lane = tid & 31, w = tid >> 5;
        const int g = lane >> 2, tg = lane & 3;
        const int wm = (w & 3) * 16, wnb = (w >> 2) * 32;

        auto cpB3 = [&](int kh, int buf) {
            const uint4* src = (const uint4*)(g_b3 + (size_t)kh * 1024);
            int v = tid;                       // 512 uint4
            int n = v >> 2, jp = v & 3;
            CP16(smem_u32(smem + FS_NB + buf * B3_BUF + (n * 12 + jp * 2) * 8), src + v);
        };

        cpB3(0, 0); CPCOMMIT();

        float acc[4][4];
#pragma unroll
        for (int nt = 0; nt < 4; nt++)
#pragma unroll
            for (int r = 0; r < 4; r++) acc[nt][r] = 0.f;

        for (int kh = 0; kh < 16; kh++) {
            CPWAIT0();
            __syncthreads();
            if (kh < 15) { cpB3(kh + 1, (kh + 1) & 1); CPCOMMIT(); }
            const char* Bs = smem + FS_NB + (kh & 1) * B3_BUF;

#pragma unroll
            for (int ks = 0; ks < 2; ks++) {
                uint2 V[4];
#pragma unroll
                for (int nt = 0; nt < 4; nt++)
                    V[nt] = *(const uint2*)(Bs + ((wnb + nt * 8 + g) * 12 + ks * 4 + tg) * 8);

                int kk = kh * 32 + ks * 16 + 2 * tg;
                float2 w0 = *(const float2*)&WN[(wm + g) * 520 + kk];
                float2 w1 = *(const float2*)&WN[(wm + g + 8) * 520 + kk];
                float2 w2 = *(const float2*)&WN[(wm + g) * 520 + kk + 8];
                float2 w3 = *(const float2*)&WN[(wm + g + 8) * 520 + kk + 8];

                uint32_t a0h = hpack(w0.x, w0.y), a1h = hpack(w1.x, w1.y);
                uint32_t a2h = hpack(w2.x, w2.y), a3h = hpack(w3.x, w3.y);
                __half2 h0 = *reinterpret_cast<__half2*>(&a0h);
                __half2 h1 = *reinterpret_cast<__half2*>(&a1h);
                __half2 h2 = *reinterpret_cast<__half2*>(&a2h);
                __half2 h3 = *reinterpret_cast<__half2*>(&a3h);
                uint32_t a0l = hpack(w0.x - __half2float(__low2half(h0)), w0.y - __half2float(__high2half(h0)));
                uint32_t a1l = hpack(w1.x - __half2float(__low2half(h1)), w1.y - __half2float(__high2half(h1)));
                uint32_t a2l = hpack(w2.x - __half2float(__low2half(h2)), w2.y - __half2float(__high2half(h2)));
                uint32_t a3l = hpack(w3.x - __half2float(__low2half(h3)), w3.y - __half2float(__high2half(h3)));

#pragma unroll
                for (int nt = 0; nt < 4; nt++) {
                    mma_fp16(acc[nt], a0h, a1h, a2h, a3h, V[nt].x, V[nt].y);
                    mma_fp16(acc[nt], a0l, a1l, a2l, a3l, V[nt].x, V[nt].y);
                }
            }
        }

#pragma unroll
        for (int nt = 0; nt < 4; nt++) {
            const float* c = acc[nt];
            size_t row = (size_t)blockIdx.x * 64 + wm + g;
            int col = 128 + wnb + nt * 8 + 2 * tg;
            *(float2*)(dOut + row * 256 + col) = make_float2(c[0], c[1]);
            *(float2*)(dOut + (row + 8) * 256 + col) = make_float2(c[2], c[3]);
        }
    }
}

// ============================================================
extern "C" void kernel_launch(void* const* d_in, const int* in_sizes, int n_in,
                              void* d_out, int out_size) {
    const float* center = (const float*)d_in[0];
    const float* nbr    = (const float*)d_in[1];
    const float* ew     = (const float*)d_in[2];
    const float* Wc     = (const float*)d_in[3];
    const float* Wn     = (const float*)d_in[4];
    const float* Wv     = (const float*)d_in[5];
    const float* Wo     = (const float*)d_in[6];
    const float* Wco    = (const float*)d_in[7];
    float* out = (float*)d_out;

    const int B = in_sizes[0] / 256;

    cudaFuncSetAttribute(k_gemm1, cudaFuncAttributeMaxDynamicSharedMemorySize, K1_SMEM);
    cudaFuncSetAttribute(k_fused, cudaFuncAttributeMaxDynamicSharedMemorySize, FS_TOTAL);

    k_prep_b1<<<320, 128>>>(Wc, Wn, Wco);
    k_prep_b3<<<128, 128>>>(Wo, Wv);

    k_gemm1<<<dim3(5, B / 128), 256, K1_SMEM>>>(center, out);
    k_fused<<<B / 64, 512, FS_TOTAL>>>(nbr, ew, out);
}

// round 6
// speedup vs baseline: 1.0974x; 1.0974x over previous
#include <cuda_runtime.h>
#include <cuda_fp16.h>
#include <cstdint>

#define BMAX 131072
#define NC   8

// ---- scratch ----
__device__ float g_qw[(size_t)BMAX * 512];
__device__ float g_wn[(size_t)BMAX * 512];
__device__ uint2 g_b1[5 * 8 * 128 * 8];   // K1 B: [ntile5][kh8][n128][j8] fp16 pairs
__device__ uint2 g_b3[16 * 128 * 8];      // K3 B: [kh16][n128][j8]

// ---- streams/events (created once at load; host objects, no device mem) ----
static cudaStream_t g_s1, g_s2;
static cudaEvent_t g_evA[NC], g_evN[NC], g_evEnd;
namespace {
struct SInit {
    SInit() {
        cudaStreamCreateWithFlags(&g_s1, cudaStreamNonBlocking);
        cudaStreamCreateWithFlags(&g_s2, cudaStreamNonBlocking);
        for (int i = 0; i < NC; i++) {
            cudaEventCreateWithFlags(&g_evA[i], cudaEventDisableTiming);
            cudaEventCreateWithFlags(&g_evN[i], cudaEventDisableTiming);
        }
        cudaEventCreateWithFlags(&g_evEnd, cudaEventDisableTiming);
    }
};
SInit g_sinit;
}

// ============================================================
// helpers
// ============================================================
__device__ __forceinline__ uint32_t smem_u32(const void* p) {
    uint32_t a;
    asm("{ .reg .u64 t; cvta.to.shared.u64 t, %1; cvt.u32.u64 %0, t; }" : "=r"(a) : "l"(p));
    return a;
}
__device__ __forceinline__ uint32_t hpack(float a, float b) {
    __half2 h = __floats2half2_rn(a, b);
    return *reinterpret_cast<uint32_t*>(&h);
}
// uint4 = { hi(a,b), hi(c,d), lo(a,b), lo(c,d) }
__device__ __forceinline__ uint4 mk4h(float a, float b, float c, float d) {
    uint4 u;
    u.x = hpack(a, b);
    u.y = hpack(c, d);
    __half2 hx = *reinterpret_cast<__half2*>(&u.x);
    __half2 hy = *reinterpret_cast<__half2*>(&u.y);
    u.z = hpack(a - __half2float(__low2half(hx)), b - __half2float(__high2half(hx)));
    u.w = hpack(c - __half2float(__low2half(hy)), d - __half2float(__high2half(hy)));
    return u;
}
__device__ __forceinline__ void mma_fp16(float* c,
                                         uint32_t a0, uint32_t a1, uint32_t a2, uint32_t a3,
                                         uint32_t b0, uint32_t b1) {
    asm volatile(
        "mma.sync.aligned.m16n8k16.row.col.f32.f16.f16.f32 "
        "{%0,%1,%2,%3},{%4,%5,%6,%7},{%8,%9},{%0,%1,%2,%3};\n"
        : "+f"(c[0]), "+f"(c[1]), "+f"(c[2]), "+f"(c[3])
        : "r"(a0), "r"(a1), "r"(a2), "r"(a3), "r"(b0), "r"(b1));
}
#define CP16(dst, src) \
    asm volatile("cp.async.cg.shared.global [%0], [%1], 16;\n" :: "r"(dst), "l"(src) : "memory")
#define CPCOMMIT() asm volatile("cp.async.commit_group;\n" ::: "memory")
#define CPWAIT0()  asm volatile("cp.async.wait_group 0;\n" ::: "memory")

// ============================================================
// Prep: fold weights -> fp16 fragment layout (hi plane only)
// ============================================================
__global__ void k_prep_b1(const float* __restrict__ Wc, const float* __restrict__ Wn,
                          const float* __restrict__ Wco) {
    int idx = blockIdx.x * 128 + threadIdx.x;      // 40960
    if (idx >= 5 * 8 * 128 * 8) return;
    int j = idx & 7, n_local = (idx >> 3) & 127, kh = (idx >> 10) & 7, ntile = idx >> 13;
    int n = ntile * 128 + n_local;
    int ks = j >> 2, tg = j & 3, kp = ks * 8 + tg;
    int k0 = kh * 32 + 2 * kp;
    int kk[4] = {k0, k0 + 1, k0 + 8, k0 + 9};
    float v[4];
    if (n < 512) {
        int h = n >> 8, j2 = n & 255;
#pragma unroll
        for (int t = 0; t < 4; t++) {
            float s = 0.f;
#pragma unroll 8
            for (int a = 0; a < 64; a++)
                s = fmaf(Wc[(h * 64 + a) * 256 + kk[t]], Wn[(h * 64 + a) * 256 + j2], s);
            v[t] = s;
        }
    } else {
#pragma unroll
        for (int t = 0; t < 4; t++) v[t] = Wco[(n - 512) * 256 + kk[t]];
    }
    g_b1[idx] = make_uint2(hpack(v[0], v[1]), hpack(v[2], v[3]));
}

__global__ void k_prep_b3(const float* __restrict__ Wo, const float* __restrict__ Wv) {
    int idx = blockIdx.x * 128 + threadIdx.x;      // 16384
    if (idx >= 16 * 128 * 8) return;
    int j = idx & 7, n = (idx >> 3) & 127, kh = idx >> 10;
    int ks = j >> 2, tg = j & 3, kp = ks * 8 + tg;
    int k0 = kh * 32 + 2 * kp;
    int kk[4] = {k0, k0 + 1, k0 + 8, k0 + 9};
    float v[4];
#pragma unroll
    for (int t = 0; t < 4; t++) {
        int k = kk[t];
        int h = k >> 8, ii = k & 255;
        float s = 0.f;
#pragma unroll 8
        for (int d = 0; d < 128; d++)
            s = fmaf(Wo[n * 256 + h * 128 + d], Wv[(h * 128 + d) * 256 + ii], s);
        v[t] = s;
    }
    g_b3[idx] = make_uint2(hpack(v[0], v[1]), hpack(v[2], v[3]));
}

// ============================================================
// 2-pass fp16 GEMM. Tile 128x128, BK=32, 256 thr.
// MODE 0 (KD=256): A=center, B=g_b1[bn]: bn<4 -> g_qw, bn==4 -> out[:,0:128]
// MODE 1 (KD=512): A=g_wn,   B=g_b3        -> out[:,128:256]
// ============================================================
#define K1_STAGE 36864
#define K1_SMEM  (2 * K1_STAGE)

template <int KD, int MODE>
__global__ __launch_bounds__(256) void k_gemm(const float* __restrict__ Ain,
                                              float* __restrict__ dOut, int row0) {
    extern __shared__ __align__(16) char smem[];
    const int tid = threadIdx.x, lid = tid & 31, w = tid >> 5;
    const int g = lid >> 2, tg = lid & 3;
    const int wm = (w & 1) * 64, wnn = (w >> 1) * 32;
    const int bn = blockIdx.x, bm = blockIdx.y;

    const float* Afp = (MODE == 0) ? Ain : g_wn;
    const uint2* Bb = (MODE == 0) ? (g_b1 + (size_t)bn * 8 * 1024) : g_b3;
    const float* Ab = Afp + (size_t)(row0 + bm * 128) * KD;

    const int arow = tid >> 1, aks = tid & 1;

#define AS_PTR(s, m, j) ((uint4*)(smem + (s) * K1_STAGE + ((m) * 12 + (j)) * 16))
#define BS_PTR(s, n, j) ((uint2*)(smem + (s) * K1_STAGE + 24576 + ((n) * 12 + (j)) * 8))

    float4 Areg[2][4];
    auto loadA = [&](int kh, int slot) {
        const float* base = Ab + (size_t)arow * KD + kh * 32 + aks * 16;
#pragma unroll
        for (int q = 0; q < 4; q++) Areg[slot][q] = *(const float4*)(base + q * 4);
    };
    auto stsA = [&](int kh, int slot) {
        int st = kh & 1;
        float4 f0 = Areg[slot][0], f1 = Areg[slot][1], f2 = Areg[slot][2], f3 = Areg[slot][3];
        *AS_PTR(st, arow, aks * 4 + 0) = mk4h(f0.x, f0.y, f2.x, f2.y);
        *AS_PTR(st, arow, aks * 4 + 1) = mk4h(f0.z, f0.w, f2.z, f2.w);
        *AS_PTR(st, arow, aks * 4 + 2) = mk4h(f1.x, f1.y, f3.x, f3.y);
        *AS_PTR(st, arow, aks * 4 + 3) = mk4h(f1.z, f1.w, f3.z, f3.w);
    };
    auto cpB = [&](int kh) {
        int st = kh & 1;
        const uint4* src = (const uint4*)(Bb + (size_t)kh * 1024);
#pragma unroll
        for (int i = 0; i < 2; i++) {
            int v = tid + 256 * i;              // 0..511 uint4
            int n = v >> 2, jp = v & 3;
            CP16(smem_u32((char*)BS_PTR(st, n, jp * 2)), src + v);
        }
    };

    cpB(0); CPCOMMIT();
    loadA(0, 0);
    stsA(0, 0);
    loadA(1, 1);
    CPWAIT0();
    __syncthreads();

    float acc[4][4][4];
#pragma unroll
    for (int i = 0; i < 4; i++)
#pragma unroll
        for (int jn = 0; jn < 4; jn++)
#pragma unroll
            for (int r = 0; r < 4; r++) acc[i][jn][r] = 0.f;

    const int NI = KD / 32;
    for (int kh = 0; kh < NI; kh++) {
        const int cur = kh & 1;
        if (kh + 1 < NI) { cpB(kh + 1); CPCOMMIT(); stsA(kh + 1, (kh + 1) & 1); }
        if (kh + 2 < NI) loadA(kh + 2, kh & 1);

#pragma unroll
        for (int ks = 0; ks < 2; ks++) {
            uint2 V[4];
#pragma unroll
            for (int nt = 0; nt < 4; nt++)
                V[nt] = *BS_PTR(cur, wnn + nt * 8 + g, ks * 4 + tg);
#pragma unroll
            for (int mt = 0; mt < 4; mt++) {
                uint4 U0 = *AS_PTR(cur, wm + mt * 16 + g, ks * 4 + tg);
                uint4 U1 = *AS_PTR(cur, wm + mt * 16 + g + 8, ks * 4 + tg);
#pragma unroll
                for (int nt = 0; nt < 4; nt++) {
                    float* c = acc[mt][nt];
                    mma_fp16(c, U0.x, U1.x, U0.y, U1.y, V[nt].x, V[nt].y);  // hi
                    mma_fp16(c, U0.z, U1.z, U0.w, U1.w, V[nt].x, V[nt].y);  // lo
                }
            }
        }
        if (kh + 1 < NI) CPWAIT0();
        __syncthreads();
    }

#pragma unroll
    for (int mt = 0; mt < 4; mt++) {
#pragma unroll
        for (int nt = 0; nt < 4; nt++) {
            const float* c = acc[mt][nt];
            int row = row0 + bm * 128 + wm + mt * 16 + g;
            int coll = wnn + nt * 8 + 2 * tg;
            float2 v0 = make_float2(c[0], c[1]);
            float2 v1 = make_float2(c[2], c[3]);
            if (MODE == 0) {
                if (bn < 4) {
                    int col = bn * 128 + coll;
                    *(float2*)(g_qw + (size_t)row * 512 + col) = v0;
                    *(float2*)(g_qw + (size_t)(row + 8) * 512 + col) = v1;
                } else {
                    *(float2*)(dOut + (size_t)row * 256 + coll) = v0;
                    *(float2*)(dOut + (size_t)(row + 8) * 256 + coll) = v1;
                }
            } else {
                *(float2*)(dOut + (size_t)row * 256 + 128 + coll) = v0;
                *(float2*)(dOut + (size_t)(row + 8) * 256 + 128 + coll) = v1;
            }
        }
    }
#undef AS_PTR
#undef BS_PTR
}

// ============================================================
// K2: attention (R4-proven). Block = one b, 128 threads.
// ============================================================
__global__ __launch_bounds__(128) void k_attn(const float* __restrict__ nb_g,
                                              const float* __restrict__ ew_g, int b0) {
    const int b = b0 + blockIdx.x;
    __shared__ float nb_s[16 * 260];
    __shared__ float qw_s[512];
    __shared__ float ews[16];
    __shared__ float sc[2][16];
    __shared__ float at[2][16];

    const int tid = threadIdx.x;
    const int k = tid >> 3, s = tid & 7;

    *(float4*)&qw_s[tid * 4] = ((const float4*)(g_qw + (size_t)b * 512))[tid];
    if (tid < 16) ews[tid] = ew_g[(size_t)b * 16 + tid];
    __syncthreads();

    const float4* nb4 = (const float4*)(nb_g + (size_t)b * 4096);
    float p0 = 0.f, p1 = 0.f;
#pragma unroll
    for (int j = 0; j < 8; j++) {
        int c4 = s + 8 * j;
        float4 x = nb4[k * 64 + c4];
        *(float4*)&nb_s[k * 260 + c4 * 4] = x;
        float4 q0 = *(const float4*)&qw_s[c4 * 4];
        float4 q1 = *(const float4*)&qw_s[256 + c4 * 4];
        p0 = fmaf(x.x, q0.x, p0); p0 = fmaf(x.y, q0.y, p0);
        p0 = fmaf(x.z, q0.z, p0); p0 = fmaf(x.w, q0.w, p0);
        p1 = fmaf(x.x, q1.x, p1); p1 = fmaf(x.y, q1.y, p1);
        p1 = fmaf(x.z, q1.z, p1); p1 = fmaf(x.w, q1.w, p1);
    }
#pragma unroll
    for (int o = 1; o <= 4; o <<= 1) {
        p0 += __shfl_xor_sync(0xffffffffu, p0, o);
        p1 += __shfl_xor_sync(0xffffffffu, p1, o);
    }
    if (s == 0) {
        sc[0][k] = p0 * 0.125f + ews[k];
        sc[1][k] = p1 * 0.125f + ews[k];
    }
    __syncthreads();

    if (tid < 32) {
        int hh = tid >> 4, kk = tid & 15;
        float v = sc[hh][kk];
        float m = v;
#pragma unroll
        for (int o = 8; o >= 1; o >>= 1)
            m = fmaxf(m, __shfl_xor_sync(0xffffffffu, m, o));
        float e = __expf(v - m);
        float sum = e;
#pragma unroll
        for (int o = 8; o >= 1; o >>= 1)
            sum += __shfl_xor_sync(0xffffffffu, sum, o);
        at[hh][kk] = e / sum;
    }
    __syncthreads();

    {
        int hh = tid >> 6;
        int cc = (tid * 4) & 255;
        float4 acc = make_float4(0.f, 0.f, 0.f, 0.f);
#pragma unroll
        for (int kk = 0; kk < 16; kk++) {
            float wgt = at[hh][kk];
            float4 x = *(const float4*)&nb_s[kk * 260 + cc];
            acc.x = fmaf(wgt, x.x, acc.x);
            acc.y = fmaf(wgt, x.y, acc.y);
            acc.z = fmaf(wgt, x.z, acc.z);
            acc.w = fmaf(wgt, x.w, acc.w);
        }
        *(float4*)(g_wn + (size_t)b * 512 + tid * 4) = acc;
    }
}

// ============================================================
extern "C" void kernel_launch(void* const* d_in, const int* in_sizes, int n_in,
                              void* d_out, int out_size) {
    const float* center = (const float*)d_in[0];
    const float* nbr    = (const float*)d_in[1];
    const float* ew     = (const float*)d_in[2];
    const float* Wc     = (const float*)d_in[3];
    const float* Wn     = (const float*)d_in[4];
    const float* Wv     = (const float*)d_in[5];
    const float* Wo     = (const float*)d_in[6];
    const float* Wco    = (const float*)d_in[7];
    float* out = (float*)d_out;

    const int B = in_sizes[0] / 256;
    const int CH = B / NC;

    cudaFuncSetAttribute(k_gemm<256, 0>, cudaFuncAttributeMaxDynamicSharedMemorySize, K1_SMEM);
    cudaFuncSetAttribute(k_gemm<512, 1>, cudaFuncAttributeMaxDynamicSharedMemorySize, K1_SMEM);

    // prep on the capture (default) stream
    k_prep_b1<<<320, 128>>>(Wc, Wn, Wco);
    k_prep_b3<<<128, 128>>>(Wo, Wv);

    // chunked pipeline: K1 on stream 0, attn on s1, K3 on s2
    for (int c = 0; c < NC; c++) {
        const int row0 = c * CH;
        k_gemm<256, 0><<<dim3(5, CH / 128), 256, K1_SMEM>>>(center, out, row0);
        cudaEventRecord(g_evA[c], 0);

        cudaStreamWaitEvent(g_s1, g_evA[c], 0);
        k_attn<<<CH, 128, 0, g_s1>>>(nbr, ew, row0);
        cudaEventRecord(g_evN[c], g_s1);

        cudaStreamWaitEvent(g_s2, g_evN[c], 0);
        k_gemm<512, 1><<<dim3(1, CH / 128), 256, K1_SMEM, g_s2>>>(nullptr, out, row0);
    }
    cudaEventRecord(g_evEnd, g_s2);
    cudaStreamWaitEvent(0, g_evEnd, 0);
}

// round 7
// speedup vs baseline: 1.4124x; 1.2870x over previous
#include <cuda_runtime.h>
#include <cuda_fp16.h>
#include <cstdint>

#define BMAX 131072
#define NC   8

// ---- scratch ----
__device__ float g_qw[(size_t)BMAX * 512];
__device__ float g_wn[(size_t)BMAX * 512];
__device__ float g_t [(size_t)BMAX * 128];
__device__ uint2 g_b0[2 * 8 * 128 * 8];   // G0 B: [nt2][kh8][n128][j8]  (Wc | Wco)
__device__ uint2 g_bn[4 * 2 * 128 * 8];   // G1 B: [nt4][kh2][n128][j8]  (Wn blockdiag)
__device__ uint2 g_b3[16 * 128 * 8];      // K3 B: [kh16][n128][j8]      (fold Wo@Wv)

// ---- streams/events ----
static cudaStream_t g_s1, g_s2;
static cudaEvent_t g_evA[NC], g_evN[NC], g_evP, g_evEnd;
namespace {
struct SInit {
    SInit() {
        cudaStreamCreateWithFlags(&g_s1, cudaStreamNonBlocking);
        cudaStreamCreateWithFlags(&g_s2, cudaStreamNonBlocking);
        for (int i = 0; i < NC; i++) {
            cudaEventCreateWithFlags(&g_evA[i], cudaEventDisableTiming);
            cudaEventCreateWithFlags(&g_evN[i], cudaEventDisableTiming);
        }
        cudaEventCreateWithFlags(&g_evP, cudaEventDisableTiming);
        cudaEventCreateWithFlags(&g_evEnd, cudaEventDisableTiming);
    }
};
SInit g_sinit;
}

// ============================================================
// helpers
// ============================================================
__device__ __forceinline__ uint32_t smem_u32(const void* p) {
    uint32_t a;
    asm("{ .reg .u64 t; cvta.to.shared.u64 t, %1; cvt.u32.u64 %0, t; }" : "=r"(a) : "l"(p));
    return a;
}
__device__ __forceinline__ uint32_t hpack(float a, float b) {
    __half2 h = __floats2half2_rn(a, b);
    return *reinterpret_cast<uint32_t*>(&h);
}
__device__ __forceinline__ uint4 mk4h(float a, float b, float c, float d) {
    uint4 u;
    u.x = hpack(a, b);
    u.y = hpack(c, d);
    __half2 hx = *reinterpret_cast<__half2*>(&u.x);
    __half2 hy = *reinterpret_cast<__half2*>(&u.y);
    u.z = hpack(a - __half2float(__low2half(hx)), b - __half2float(__high2half(hx)));
    u.w = hpack(c - __half2float(__low2half(hy)), d - __half2float(__high2half(hy)));
    return u;
}
__device__ __forceinline__ void mma_fp16(float* c,
                                         uint32_t a0, uint32_t a1, uint32_t a2, uint32_t a3,
                                         uint32_t b0, uint32_t b1) {
    asm volatile(
        "mma.sync.aligned.m16n8k16.row.col.f32.f16.f16.f32 "
        "{%0,%1,%2,%3},{%4,%5,%6,%7},{%8,%9},{%0,%1,%2,%3};\n"
        : "+f"(c[0]), "+f"(c[1]), "+f"(c[2]), "+f"(c[3])
        : "r"(a0), "r"(a1), "r"(a2), "r"(a3), "r"(b0), "r"(b1));
}
#define CP16(dst, src) \
    asm volatile("cp.async.cg.shared.global [%0], [%1], 16;\n" :: "r"(dst), "l"(src) : "memory")
#define CPCOMMIT() asm volatile("cp.async.commit_group;\n" ::: "memory")
#define CPWAIT0()  asm volatile("cp.async.wait_group 0;\n" ::: "memory")
#define CPWAIT1()  asm volatile("cp.async.wait_group 1;\n" ::: "memory")

// ============================================================
// Preps (all trivial requantize except b3 fold)
// j = ks*4+tg -> k-values kh*32 + ks*16 + {2tg, 2tg+1, 2tg+8, 2tg+9}
// ============================================================
__global__ void k_prep_b0(const float* __restrict__ Wc, const float* __restrict__ Wco) {
    int idx = blockIdx.x * 256 + threadIdx.x;      // 16384
    if (idx >= 2 * 8 * 128 * 8) return;
    int j = idx & 7, n = (idx >> 3) & 127, kh = (idx >> 10) & 7, nt = idx >> 13;
    int ks = j >> 2, tg = j & 3;
    int k0 = kh * 32 + ks * 16 + 2 * tg;
    const float* src = nt ? Wco : Wc;
    float v0 = src[n * 256 + k0],     v1 = src[n * 256 + k0 + 1];
    float v2 = src[n * 256 + k0 + 8], v3 = src[n * 256 + k0 + 9];
    g_b0[idx] = make_uint2(hpack(v0, v1), hpack(v2, v3));
}

__global__ void k_prep_bn(const float* __restrict__ Wn) {
    int idx = blockIdx.x * 256 + threadIdx.x;      // 8192
    if (idx >= 4 * 2 * 128 * 8) return;
    int j = idx & 7, n = (idx >> 3) & 127, kh = (idx >> 10) & 1, nt = idx >> 11;
    int col = nt * 128 + n;
    int h = col >> 8, j2 = col & 255;
    int ks = j >> 2, tg = j & 3;
    int a0 = kh * 32 + ks * 16 + 2 * tg;
    float v0 = Wn[(h * 64 + a0) * 256 + j2],     v1 = Wn[(h * 64 + a0 + 1) * 256 + j2];
    float v2 = Wn[(h * 64 + a0 + 8) * 256 + j2], v3 = Wn[(h * 64 + a0 + 9) * 256 + j2];
    g_bn[idx] = make_uint2(hpack(v0, v1), hpack(v2, v3));
}

// K3 fold: M[n][i] = sum_d Wo[n][h*128+d] * Wv[(h*128+d)][i].  One block per kh (16).
#define P3_WO   0                         // Wo_t[d128][n132] fp32 (transposed)
#define P3_WV   (128 * 132 * 4)           // Wv_s[d128][i36]
#define P3_PART (P3_WV + 128 * 36 * 4)    // part[2][n128][i32]
#define P3_SMEM (P3_PART + 2 * 128 * 32 * 4)

__global__ void k_prep_b3(const float* __restrict__ Wo, const float* __restrict__ Wv) {
    extern __shared__ __align__(16) char sm3[];
    float* Wo_t = (float*)(sm3 + P3_WO);
    float* Wv_s = (float*)(sm3 + P3_WV);
    float* part = (float*)(sm3 + P3_PART);
    const int kh = blockIdx.x;
    const int h = kh >> 3;
    const int iwin = (kh * 32) & 255;
    const int tid = threadIdx.x;

    // load Wo tile transposed: Wo_t[d][n] = Wo[n][h*128+d]
    for (int i = tid; i < 4096; i += 256) {         // i over (n, d4)
        int n = i >> 5, d4 = i & 31;
        float4 x = *(const float4*)(Wo + n * 256 + h * 128 + d4 * 4);
        Wo_t[(d4 * 4 + 0) * 132 + n] = x.x;
        Wo_t[(d4 * 4 + 1) * 132 + n] = x.y;
        Wo_t[(d4 * 4 + 2) * 132 + n] = x.z;
        Wo_t[(d4 * 4 + 3) * 132 + n] = x.w;
    }
    // load Wv tile: Wv_s[d][i] = Wv[(h*128+d)][iwin+i], i<32
    for (int i = tid; i < 1024; i += 256) {         // (d, i4)
        int d = i >> 3, i4 = i & 7;
        float4 x = *(const float4*)(Wv + (h * 128 + d) * 256 + iwin + i4 * 4);
        *(float4*)&Wv_s[d * 36 + i4 * 4] = x;
    }
    __syncthreads();

    // partial sums: thread (n, half) accumulates 32 i over 64 d
    {
        int n = tid & 127, half = tid >> 7;
        float acc[32];
#pragma unroll
        for (int i = 0; i < 32; i++) acc[i] = 0.f;
        for (int d = half * 64; d < half * 64 + 64; d++) {
            float wo = Wo_t[d * 132 + n];
#pragma unroll
            for (int i4 = 0; i4 < 8; i4++) {
                float4 wv = *(const float4*)&Wv_s[d * 36 + i4 * 4];
                acc[i4 * 4 + 0] = fmaf(wo, wv.x, acc[i4 * 4 + 0]);
                acc[i4 * 4 + 1] = fmaf(wo, wv.y, acc[i4 * 4 + 1]);
                acc[i4 * 4 + 2] = fmaf(wo, wv.z, acc[i4 * 4 + 2]);
                acc[i4 * 4 + 3] = fmaf(wo, wv.w, acc[i4 * 4 + 3]);
            }
        }
#pragma unroll
        for (int i = 0; i < 32; i++) part[(half * 128 + n) * 32 + i] = acc[i];
    }
    __syncthreads();

    // combine + quantize -> g_b3[kh][n][j]
    for (int o = tid; o < 1024; o += 256) {
        int j = o & 7, n = o >> 3;
        int ks = j >> 2, tg = j & 3;
        int i0 = ks * 16 + 2 * tg;
        float v0 = part[n * 32 + i0]     + part[(128 + n) * 32 + i0];
        float v1 = part[n * 32 + i0 + 1] + part[(128 + n) * 32 + i0 + 1];
        float v2 = part[n * 32 + i0 + 8] + part[(128 + n) * 32 + i0 + 8];
        float v3 = part[n * 32 + i0 + 9] + part[(128 + n) * 32 + i0 + 9];
        g_b3[kh * 1024 + n * 8 + j] = make_uint2(hpack(v0, v1), hpack(v2, v3));
    }
}

// ============================================================
// 2-pass fp16 GEMM, swizzled 128B-row A smem. Tile 128x128, BK=32, 256 thr.
// MODE 0 (KD=256): A=center, B=g_b0: bn0 -> g_t, bn1 -> out[:,0:128]
// MODE 1 (KD=512): A=g_wn,   B=g_b3  -> out[:,128:256]
// smem/stage: A 16KB (128B rows, XOR swizzle) + B 8KB (64B rows) = 24KB; x2 = 48KB
// ============================================================
#define GSTAGE 24576
#define GSMEM  (2 * GSTAGE)
#define AS_ADDR(sm, s, m, j) ((sm) + (s) * GSTAGE + (m) * 128 + (((j) ^ ((m) & 7)) * 16))
#define BS_ADDR(sm, s, n, j) ((sm) + (s) * GSTAGE + 16384 + (n) * 64 + (j) * 8)

template <int KD, int MODE>
__global__ __launch_bounds__(256) void k_gemm(const float* __restrict__ Ain,
                                              float* __restrict__ dOut, int row0) {
    extern __shared__ __align__(16) char smem[];
    const int tid = threadIdx.x, lid = tid & 31, w = tid >> 5;
    const int g = lid >> 2, tg = lid & 3;
    const int wm = (w & 1) * 64, wnn = (w >> 1) * 32;
    const int bn = blockIdx.x, bm = blockIdx.y;

    const float* Afp = (MODE == 0) ? Ain : g_wn;
    const uint2* Bb = (MODE == 0) ? (g_b0 + (size_t)bn * 8 * 1024) : g_b3;
    const float* Ab = Afp + (size_t)(row0 + bm * 128) * KD;

    const int arow = tid >> 1, aks = tid & 1;

    float4 Areg[2][4];
    auto loadA = [&](int kh, int slot) {
        const float* base = Ab + (size_t)arow * KD + kh * 32 + aks * 16;
#pragma unroll
        for (int q = 0; q < 4; q++) Areg[slot][q] = *(const float4*)(base + q * 4);
    };
    auto stsA = [&](int kh, int slot) {
        int st = kh & 1;
        float4 f0 = Areg[slot][0], f1 = Areg[slot][1], f2 = Areg[slot][2], f3 = Areg[slot][3];
        *(uint4*)AS_ADDR(smem, st, arow, aks * 4 + 0) = mk4h(f0.x, f0.y, f2.x, f2.y);
        *(uint4*)AS_ADDR(smem, st, arow, aks * 4 + 1) = mk4h(f0.z, f0.w, f2.z, f2.w);
        *(uint4*)AS_ADDR(smem, st, arow, aks * 4 + 2) = mk4h(f1.x, f1.y, f3.x, f3.y);
        *(uint4*)AS_ADDR(smem, st, arow, aks * 4 + 3) = mk4h(f1.z, f1.w, f3.z, f3.w);
    };
    auto cpB = [&](int kh) {
        int st = kh & 1;
        const char* src = (const char*)Bb + (size_t)kh * 8192;
#pragma unroll
        for (int i = 0; i < 2; i++) {
            int v = tid + 256 * i;              // 512 x 16B
            CP16(smem_u32(smem + st * GSTAGE + 16384 + v * 16), src + v * 16);
        }
    };

    cpB(0); CPCOMMIT();
    loadA(0, 0);
    stsA(0, 0);
    loadA(1, 1);
    CPWAIT0();
    __syncthreads();

    float acc[4][4][4];
#pragma unroll
    for (int i = 0; i < 4; i++)
#pragma unroll
        for (int jn = 0; jn < 4; jn++)
#pragma unroll
            for (int r = 0; r < 4; r++) acc[i][jn][r] = 0.f;

    const int NI = KD / 32;
    for (int kh = 0; kh < NI; kh++) {
        const int cur = kh & 1;
        if (kh + 1 < NI) { cpB(kh + 1); CPCOMMIT(); stsA(kh + 1, (kh + 1) & 1); }
        if (kh + 2 < NI) loadA(kh + 2, kh & 1);

#pragma unroll
        for (int ks = 0; ks < 2; ks++) {
            uint2 V[4];
#pragma unroll
            for (int nt = 0; nt < 4; nt++)
                V[nt] = *(const uint2*)BS_ADDR(smem, cur, wnn + nt * 8 + g, ks * 4 + tg);
#pragma unroll
            for (int mt = 0; mt < 4; mt++) {
                uint4 U0 = *(const uint4*)AS_ADDR(smem, cur, wm + mt * 16 + g, ks * 4 + tg);
                uint4 U1 = *(const uint4*)AS_ADDR(smem, cur, wm + mt * 16 + g + 8, ks * 4 + tg);
#pragma unroll
                for (int nt = 0; nt < 4; nt++) {
                    float* c = acc[mt][nt];
                    mma_fp16(c, U0.x, U1.x, U0.y, U1.y, V[nt].x, V[nt].y);  // hi
                    mma_fp16(c, U0.z, U1.z, U0.w, U1.w, V[nt].x, V[nt].y);  // lo
                }
            }
        }
        if (kh + 1 < NI) CPWAIT0();
        __syncthreads();
    }

#pragma unroll
    for (int mt = 0; mt < 4; mt++) {
#pragma unroll
        for (int nt = 0; nt < 4; nt++) {
            const float* c = acc[mt][nt];
            int row = row0 + bm * 128 + wm + mt * 16 + g;
            int coll = wnn + nt * 8 + 2 * tg;
            float2 v0 = make_float2(c[0], c[1]);
            float2 v1 = make_float2(c[2], c[3]);
            if (MODE == 0) {
                if (bn == 0) {
                    *(float2*)(g_t + (size_t)row * 128 + coll) = v0;
                    *(float2*)(g_t + (size_t)(row + 8) * 128 + coll) = v1;
                } else {
                    *(float2*)(dOut + (size_t)row * 256 + coll) = v0;
                    *(float2*)(dOut + (size_t)(row + 8) * 256 + coll) = v1;
                }
            } else {
                *(float2*)(dOut + (size_t)row * 256 + 128 + coll) = v0;
                *(float2*)(dOut + (size_t)(row + 8) * 256 + 128 + coll) = v1;
            }
        }
    }
}

// ============================================================
// G1: qW = t @ blockdiag(Wn).  M=128/CTA, N=512, K=64 per head.
// A = g_t (rows 128 wide, fp32, 2-pass split), B = g_bn.
// smem: A 4 planes x 16KB = 64KB (swizzled), B dbuf 2 x 16KB = 32KB -> 96KB
// ============================================================
#define G1A(p, m, j)      (smem + (p) * 16384 + (m) * 128 + (((j) ^ ((m) & 7)) * 16))
#define G1B(buf, kh, n, j) (smem + 65536 + (buf) * 16384 + (kh) * 8192 + (n) * 64 + (j) * 8)
#define G1_SMEM (65536 + 32768)

__global__ __launch_bounds__(256) void k_g1(float* __restrict__ dummy, int row0) {
    extern __shared__ __align__(16) char smem[];
    const int tid = threadIdx.x, lid = tid & 31, w = tid >> 5;
    const int g = lid >> 2, tg = lid & 3;
    const int wm = (w & 1) * 64, wnn = (w >> 1) * 32;
    const int bm = blockIdx.x;

    const float* Ab = g_t + (size_t)(row0 + bm * 128) * 128;
    const int arow = tid >> 1, ah = tid & 1;

    auto cpB = [&](int nt) {
        int buf = nt & 1;
        const char* src = (const char*)(g_bn + (size_t)nt * 2048);
#pragma unroll
        for (int i = 0; i < 4; i++) {
            int v = tid + 256 * i;              // 1024 x 16B
            CP16(smem_u32(smem + 65536 + buf * 16384 + v * 16), src + v * 16);
        }
    };

    cpB(0); CPCOMMIT();

    // stage all of A (128 rows x 128 k), split hi/lo
#pragma unroll
    for (int p = 0; p < 4; p++) {
        const float* base = Ab + (size_t)arow * 128 + p * 32 + ah * 16;
        float4 f0 = *(const float4*)(base + 0);
        float4 f1 = *(const float4*)(base + 4);
        float4 f2 = *(const float4*)(base + 8);
        float4 f3 = *(const float4*)(base + 12);
        *(uint4*)G1A(p, arow, ah * 4 + 0) = mk4h(f0.x, f0.y, f2.x, f2.y);
        *(uint4*)G1A(p, arow, ah * 4 + 1) = mk4h(f0.z, f0.w, f2.z, f2.w);
        *(uint4*)G1A(p, arow, ah * 4 + 2) = mk4h(f1.x, f1.y, f3.x, f3.y);
        *(uint4*)G1A(p, arow, ah * 4 + 3) = mk4h(f1.z, f1.w, f3.z, f3.w);
    }

    for (int nt = 0; nt < 4; nt++) {
        const int buf = nt & 1;
        const int h = nt >> 1;
        if (nt < 3) { cpB(nt + 1); CPCOMMIT(); CPWAIT1(); }
        else        CPWAIT0();
        __syncthreads();

        float acc[4][4];
#pragma unroll
        for (int jn = 0; jn < 4; jn++)
#pragma unroll
            for (int r = 0; r < 4; r++) acc[jn][r] = 0.f;

#pragma unroll
        for (int kh = 0; kh < 2; kh++) {
            const int p = 2 * h + kh;
#pragma unroll
            for (int ks = 0; ks < 2; ks++) {
                uint2 V[4];
#pragma unroll
                for (int n2 = 0; n2 < 4; n2++)
                    V[n2] = *(const uint2*)G1B(buf, kh, wnn + n2 * 8 + g, ks * 4 + tg);
#pragma unroll
                for (int mt = 0; mt < 4; mt++) {
                    uint4 U0 = *(const uint4*)G1A(p, wm + mt * 16 + g, ks * 4 + tg);
                    uint4 U1 = *(const uint4*)G1A(p, wm + mt * 16 + g + 8, ks * 4 + tg);
                    // accumulate per-mt into acc? -> need per-mt acc: reuse trick:
                    // acc layout [mt? no] -- we fold mt into separate epilogue regs
                    // NOTE: acc indexed [n2]; must be [mt][n2] -> handled below
                    (void)U0; (void)U1;
                }
                // full [mt][n2] accumulation (unrolled explicitly)
#pragma unroll
                for (int mt = 0; mt < 4; mt++) {
                    uint4 U0 = *(const uint4*)G1A(p, wm + mt * 16 + g, ks * 4 + tg);
                    uint4 U1 = *(const uint4*)G1A(p, wm + mt * 16 + g + 8, ks * 4 + tg);
                    (void)U0; (void)U1;
                }
            }
        }
        // --- the above sketch replaced by the real accumulation below ---
        float accm[4][4][4];
#pragma unroll
        for (int mt = 0; mt < 4; mt++)
#pragma unroll
            for (int jn = 0; jn < 4; jn++)
#pragma unroll
                for (int r = 0; r < 4; r++) accm[mt][jn][r] = 0.f;
#pragma unroll
        for (int kh = 0; kh < 2; kh++) {
            const int p = 2 * h + kh;
#pragma unroll
            for (int ks = 0; ks < 2; ks++) {
                uint2 V[4];
#pragma unroll
                for (int n2 = 0; n2 < 4; n2++)
                    V[n2] = *(const uint2*)G1B(buf, kh, wnn + n2 * 8 + g, ks * 4 + tg);
#pragma unroll
                for (int mt = 0; mt < 4; mt++) {
                    uint4 U0 = *(const uint4*)G1A(p, wm + mt * 16 + g, ks * 4 + tg);
                    uint4 U1 = *(const uint4*)G1A(p, wm + mt * 16 + g + 8, ks * 4 + tg);
#pragma unroll
                    for (int n2 = 0; n2 < 4; n2++) {
                        float* c = accm[mt][n2];
                        mma_fp16(c, U0.x, U1.x, U0.y, U1.y, V[n2].x, V[n2].y);
                        mma_fp16(c, U0.z, U1.z, U0.w, U1.w, V[n2].x, V[n2].y);
                    }
                }
            }
        }
        __syncthreads();

#pragma unroll
        for (int mt = 0; mt < 4; mt++) {
#pragma unroll
            for (int n2 = 0; n2 < 4; n2++) {
                const float* c = accm[mt][n2];
                int row = row0 + bm * 128 + wm + mt * 16 + g;
                int col = nt * 128 + wnn + n2 * 8 + 2 * tg;
                *(float2*)(g_qw + (size_t)row * 512 + col) = make_float2(c[0], c[1]);
                *(float2*)(g_qw + (size_t)(row + 8) * 512 + col) = make_float2(c[2], c[3]);
            }
        }
    }
}

// ============================================================
// K2: attention. nb cached as half2 (wn path only); scores fp32.
// ============================================================
__global__ __launch_bounds__(128) void k_attn(const float* __restrict__ nb_g,
                                              const float* __restrict__ ew_g, int b0) {
    const int b = b0 + blockIdx.x;
    __shared__ uint2 nbh[16][68];     // row: 64 uint2 (4 fp16 each) + pad
    __shared__ float qw_s[512];
    __shared__ float ews[16];
    __shared__ float sc[2][16];
    __shared__ float at[2][16];

    const int tid = threadIdx.x;
    const int k = tid >> 3, s = tid & 7;

    *(float4*)&qw_s[tid * 4] = ((const float4*)(g_qw + (size_t)b * 512))[tid];
    if (tid < 16) ews[tid] = ew_g[(size_t)b * 16 + tid];
    __syncthreads();

    const float4* nb4 = (const float4*)(nb_g + (size_t)b * 4096);
    float p0 = 0.f, p1 = 0.f;
#pragma unroll
    for (int j = 0; j < 8; j++) {
        int c4 = s + 8 * j;
        float4 x = nb4[k * 64 + c4];
        nbh[k][c4] = make_uint2(hpack(x.x, x.y), hpack(x.z, x.w));
        float4 q0 = *(const float4*)&qw_s[c4 * 4];
        float4 q1 = *(const float4*)&qw_s[256 + c4 * 4];
        p0 = fmaf(x.x, q0.x, p0); p0 = fmaf(x.y, q0.y, p0);
        p0 = fmaf(x.z, q0.z, p0); p0 = fmaf(x.w, q0.w, p0);
        p1 = fmaf(x.x, q1.x, p1); p1 = fmaf(x.y, q1.y, p1);
        p1 = fmaf(x.z, q1.z, p1); p1 = fmaf(x.w, q1.w, p1);
    }
#pragma unroll
    for (int o = 1; o <= 4; o <<= 1) {
        p0 += __shfl_xor_sync(0xffffffffu, p0, o);
        p1 += __shfl_xor_sync(0xffffffffu, p1, o);
    }
    if (s == 0) {
        sc[0][k] = p0 * 0.125f + ews[k];
        sc[1][k] = p1 * 0.125f + ews[k];
    }
    __syncthreads();

    if (tid < 32) {
        int hh = tid >> 4, kk = tid & 15;
        float v = sc[hh][kk];
        float m = v;
#pragma unroll
        for (int o = 8; o >= 1; o >>= 1)
            m = fmaxf(m, __shfl_xor_sync(0xffffffffu, m, o));
        float e = __expf(v - m);
        float sum = e;
#pragma unroll
        for (int o = 8; o >= 1; o >>= 1)
            sum += __shfl_xor_sync(0xffffffffu, sum, o);
        at[hh][kk] = e / sum;
    }
    __syncthreads();

    {
        int hh = tid >> 6;
        int c2 = tid & 63;                 // uint2 index = 4 columns
        float4 acc = make_float4(0.f, 0.f, 0.f, 0.f);
#pragma unroll
        for (int kk = 0; kk < 16; kk++) {
            float wgt = at[hh][kk];
            uint2 u = nbh[kk][c2];
            float2 f0 = __half22float2(*reinterpret_cast<__half2*>(&u.x));
            float2 f1 = __half22float2(*reinterpret_cast<__half2*>(&u.y));
            acc.x = fmaf(wgt, f0.x, acc.x);
            acc.y = fmaf(wgt, f0.y, acc.y);
            acc.z = fmaf(wgt, f1.x, acc.z);
            acc.w = fmaf(wgt, f1.y, acc.w);
        }
        *(float4*)(g_wn + (size_t)b * 512 + tid * 4) = acc;
    }
}

// ============================================================
extern "C" void kernel_launch(void* const* d_in, const int* in_sizes, int n_in,
                              void* d_out, int out_size) {
    const float* center = (const float*)d_in[0];
    const float* nbr    = (const float*)d_in[1];
    const float* ew     = (const float*)d_in[2];
    const float* Wc     = (const float*)d_in[3];
    const float* Wn     = (const float*)d_in[4];
    const float* Wv     = (const float*)d_in[5];
    const float* Wo     = (const float*)d_in[6];
    const float* Wco    = (const float*)d_in[7];
    float* out = (float*)d_out;

    const int B = in_sizes[0] / 256;
    const int CH = B / NC;

    cudaFuncSetAttribute(k_gemm<256, 0>, cudaFuncAttributeMaxDynamicSharedMemorySize, GSMEM);
    cudaFuncSetAttribute(k_gemm<512, 1>, cudaFuncAttributeMaxDynamicSharedMemorySize, GSMEM);
    cudaFuncSetAttribute(k_g1, cudaFuncAttributeMaxDynamicSharedMemorySize, G1_SMEM);
    cudaFuncSetAttribute(k_prep_b3, cudaFuncAttributeMaxDynamicSharedMemorySize, P3_SMEM);

    k_prep_b0<<<64, 256>>>(Wc, Wco);
    k_prep_bn<<<32, 256>>>(Wn);
    k_prep_b3<<<16, 256, P3_SMEM>>>(Wo, Wv);
    cudaEventRecord(g_evP, 0);
    cudaStreamWaitEvent(g_s2, g_evP, 0);

    for (int c = 0; c < NC; c++) {
        const int row0 = c * CH;
        k_gemm<256, 0><<<dim3(2, CH / 128), 256, GSMEM>>>(center, out, row0);
        k_g1<<<CH / 128, 256, G1_SMEM>>>(nullptr, row0);
        cudaEventRecord(g_evA[c], 0);

        cudaStreamWaitEvent(g_s1, g_evA[c], 0);
        k_attn<<<CH, 128, 0, g_s1>>>(nbr, ew, row0);
        cudaEventRecord(g_evN[c], g_s1);

        cudaStreamWaitEvent(g_s2, g_evN[c], 0);
        k_gemm<512, 1><<<dim3(1, CH / 128), 256, GSMEM, g_s2>>>(nullptr, out, row0);
    }
    cudaEventRecord(g_evEnd, g_s2);
    cudaStreamWaitEvent(0, g_evEnd, 0);
}